// round 1
// baseline (speedup 1.0000x reference)
#include <cuda_runtime.h>

// INRF_32332513804468
// out[b,i,j,f] = sum_pq M2[ij,pq]*x[b,pq,f]
//              - sum_pq W2[ij,pq]*relu( x[b,pq,f] - shifted[b,pq,ij,f] )
// shifted[b,pq,ij,f] = sum_{kh,kw,c} x[b, p+kh-1, q+kw-1, c] * G[ij, kh,kw,c,f]  (SAME zero pad)
//
// Shapes: B=4, H=W=32 (HW=1024), C=F=16, KH=KW=3.
// inputs: [B,32,32,16]   M,Wp: [32,32,1,32,32,1] -> [ij][pq]   G: [32,32,3,3,16,16]
//
// Block = (ij, b). Stage batch input (transposed [c][pq], stride 1025), G[ij],
// M2/W2 rows in smem. 256 threads x 4 pq each; fused conv + relu + reductions.

#define HW   1024
#define NC   16
#define NF   16
#define STR  1025   // smem row stride (pad to kill bank conflicts)

__global__ __launch_bounds__(256, 2)
void inrf_kernel(const float* __restrict__ gin,
                 const float* __restrict__ gM,
                 const float* __restrict__ gW,
                 const float* __restrict__ gG,
                 float* __restrict__ gout)
{
    extern __shared__ float sm[];
    float* s_in  = sm;                 // 16*1025 = 16400 floats (input, [c][pq])
    float* s_G   = s_in + NC * STR;    // 2304 floats ([kh*3+kw][c][f])
    float* s_W   = s_G + 2304;         // 1024
    float* s_M   = s_W + 1024;         // 1024
    float* s_red = s_M + 1024;         // 8*16

    const int t  = threadIdx.x;
    const int ij = blockIdx.x;
    const int b  = blockIdx.y;

    // --- stage input, transposed to [c][pq] ---
    const float* in_b = gin + (size_t)b * (HW * NC);
    for (int idx = t; idx < HW * NC; idx += 256) {
        int c  = idx & 15;
        int pq = idx >> 4;
        s_in[c * STR + pq] = in_b[idx];
    }
    // --- stage G[ij] (2304 contiguous floats) ---
    const float* Gij = gG + (size_t)ij * 2304;
    for (int idx = t; idx < 2304; idx += 256) s_G[idx] = Gij[idx];
    // --- stage M2/W2 rows ---
    const float* Wij = gW + (size_t)ij * 1024;
    const float* Mij = gM + (size_t)ij * 1024;
    for (int idx = t; idx < 1024; idx += 256) {
        s_W[idx] = Wij[idx];
        s_M[idx] = Mij[idx];
    }
    __syncthreads();

    float acc[NF];
#pragma unroll
    for (int f = 0; f < NF; f++) acc[f] = 0.f;

#pragma unroll 1
    for (int k = 0; k < 4; k++) {
        const int pq = t + 256 * k;
        const int p  = pq >> 5;
        const int q  = pq & 31;

        float s[NF];
#pragma unroll
        for (int f = 0; f < NF; f++) s[f] = 0.f;

#pragma unroll 1
        for (int kh = 0; kh < 3; kh++) {
            const int pp = p + kh - 1;
            if ((unsigned)pp >= 32u) continue;
#pragma unroll 1
            for (int kw = 0; kw < 3; kw++) {
                const int qq = q + kw - 1;
                if ((unsigned)qq >= 32u) continue;
                const float*  pin = s_in + (pp * 32 + qq);
                const float4* g4  = (const float4*)(s_G + (kh * 3 + kw) * 256);
#pragma unroll
                for (int c = 0; c < NC; c++) {
                    const float pv = pin[c * STR];
                    const float4 ga = g4[c * 4 + 0];
                    const float4 gb = g4[c * 4 + 1];
                    const float4 gc = g4[c * 4 + 2];
                    const float4 gd = g4[c * 4 + 3];
                    s[0]  += pv * ga.x;  s[1]  += pv * ga.y;
                    s[2]  += pv * ga.z;  s[3]  += pv * ga.w;
                    s[4]  += pv * gb.x;  s[5]  += pv * gb.y;
                    s[6]  += pv * gb.z;  s[7]  += pv * gb.w;
                    s[8]  += pv * gc.x;  s[9]  += pv * gc.y;
                    s[10] += pv * gc.z;  s[11] += pv * gc.w;
                    s[12] += pv * gd.x;  s[13] += pv * gd.y;
                    s[14] += pv * gd.z;  s[15] += pv * gd.w;
                }
            }
        }

        const float w = s_W[pq];
        const float m = s_M[pq];
#pragma unroll
        for (int f = 0; f < NF; f++) {
            const float x = s_in[f * STR + pq];
            acc[f] += m * x - w * fmaxf(x - s[f], 0.f);
        }
    }

    // --- reduce acc over 256 threads ---
#pragma unroll
    for (int off = 16; off >= 1; off >>= 1) {
#pragma unroll
        for (int f = 0; f < NF; f++)
            acc[f] += __shfl_xor_sync(0xffffffffu, acc[f], off);
    }
    const int wid  = t >> 5;
    const int lane = t & 31;
    if (lane == 0) {
#pragma unroll
        for (int f = 0; f < NF; f++) s_red[wid * NF + f] = acc[f];
    }
    __syncthreads();
    if (t < NF) {
        float v = 0.f;
#pragma unroll
        for (int wv = 0; wv < 8; wv++) v += s_red[wv * NF + t];
        gout[((size_t)b * HW + ij) * NF + t] = v;
    }
}

extern "C" void kernel_launch(void* const* d_in, const int* in_sizes, int n_in,
                              void* d_out, int out_size)
{
    const float* inputs = (const float*)d_in[0];
    const float* M      = (const float*)d_in[1];
    const float* Wp     = (const float*)d_in[2];
    const float* G      = (const float*)d_in[3];
    float* out = (float*)d_out;

    const size_t smem = (size_t)(NC * STR + 2304 + 1024 + 1024 + 8 * NF) * sizeof(float);
    cudaFuncSetAttribute(inrf_kernel, cudaFuncAttributeMaxDynamicSharedMemorySize, (int)smem);

    dim3 grid(HW, 4);
    inrf_kernel<<<grid, 256, smem>>>(inputs, M, Wp, G, out);
}

// round 2
// speedup vs baseline: 1.7266x; 1.7266x over previous
#include <cuda_runtime.h>
#include <cstdint>

// INRF_32332513804468 — round 2: f32x2 packed FMA + G-load amortization + padded smem.
// out[b,i,j,f] = sum_pq M2[ij,pq]*x[b,pq,f] - sum_pq W2[ij,pq]*relu(x[b,pq,f]-shifted[b,pq,ij,f])
// shifted[b,pq,ij,f] = 3x3x16 conv of x with per-ij filter G[ij] (SAME, zero pad).
// B=4, H=W=32, C=F=16.

#define HW    1024
#define NC    16
#define NF    16
#define PSTR  1157          // padded plane stride: 34*34=1156 -> 1157 (conflict-free)
#define PROW  34

__global__ __launch_bounds__(256, 2)
void inrf_kernel(const float* __restrict__ gin,
                 const float* __restrict__ gM,
                 const float* __restrict__ gW,
                 const float* __restrict__ gG,
                 float* __restrict__ gout)
{
    extern __shared__ float sm[];
    float* s_pad = sm;                  // 16 * 1157 = 18512 (zero-padded [c][34x34])
    float* s_G   = s_pad + NC * PSTR;   // 2304  ([tap][c][f])
    float* s_W   = s_G + 2304;          // 1024
    float* s_M   = s_W + 1024;          // 1024
    float* s_red = s_M + 1024;          // 128

    const int t  = threadIdx.x;
    const int ij = blockIdx.x;
    const int b  = blockIdx.y;

    // ---- zero padded planes, then fill interior (transposed [c][spatial]) ----
    for (int idx = t; idx < NC * PSTR; idx += 256) s_pad[idx] = 0.f;
    __syncthreads();
    const float* in_b = gin + (size_t)b * (HW * NC);
    for (int idx = t; idx < HW * NC; idx += 256) {
        int c  = idx & 15;
        int pq = idx >> 4;
        int p  = pq >> 5, q = pq & 31;
        s_pad[c * PSTR + (p + 1) * PROW + (q + 1)] = in_b[idx];
    }
    const float* Gij = gG + (size_t)ij * 2304;
    for (int idx = t; idx < 2304; idx += 256) s_G[idx] = Gij[idx];
    const float* Wij = gW + (size_t)ij * 1024;
    const float* Mij = gM + (size_t)ij * 1024;
    for (int idx = t; idx < 1024; idx += 256) {
        s_W[idx] = Wij[idx];
        s_M[idx] = Mij[idx];
    }
    __syncthreads();

    // center offsets of this thread's 4 pixels inside a padded plane
    int cbase[4];
#pragma unroll
    for (int k = 0; k < 4; k++) {
        int pq = t + 256 * k;
        cbase[k] = ((pq >> 5) + 1) * PROW + (pq & 31) + 1;
    }

    const uint32_t sG_base  = (uint32_t)__cvta_generic_to_shared(s_G);
    const uint32_t sIn_base = (uint32_t)__cvta_generic_to_shared(s_pad);

    // conv accumulators: 4 pixels x 8 f32x2 pairs (f0..15)
    unsigned long long acc2[4][8];
#pragma unroll
    for (int k = 0; k < 4; k++)
#pragma unroll
        for (int j = 0; j < 8; j++) acc2[k][j] = 0ull;

#pragma unroll 1
    for (int tap = 0; tap < 9; tap++) {
        const int doff = (tap / 3 - 1) * PROW + (tap % 3 - 1);
        const uint32_t gtap = sG_base + (uint32_t)(tap * 256) * 4u;

#pragma unroll
        for (int c = 0; c < NC; c++) {
            // G[tap][c][0..15] as 8 packed f32x2 (two 128-bit shared loads x2)
            unsigned long long g0, g1, g2, g3, g4, g5, g6, g7;
            {
                uint32_t ga = gtap + (uint32_t)(c * 16) * 4u;
                asm volatile("ld.shared.v2.b64 {%0,%1}, [%2];"
                             : "=l"(g0), "=l"(g1) : "r"(ga));
                asm volatile("ld.shared.v2.b64 {%0,%1}, [%2];"
                             : "=l"(g2), "=l"(g3) : "r"(ga + 16u));
                asm volatile("ld.shared.v2.b64 {%0,%1}, [%2];"
                             : "=l"(g4), "=l"(g5) : "r"(ga + 32u));
                asm volatile("ld.shared.v2.b64 {%0,%1}, [%2];"
                             : "=l"(g6), "=l"(g7) : "r"(ga + 48u));
            }
            const uint32_t pa = sIn_base + (uint32_t)(c * PSTR + doff) * 4u;

#pragma unroll
            for (int k = 0; k < 4; k++) {
                float pv;
                asm volatile("ld.shared.f32 %0, [%1];"
                             : "=f"(pv) : "r"(pa + (uint32_t)cbase[k] * 4u));
                unsigned long long pp;
                asm volatile("mov.b64 %0, {%1, %1};" : "=l"(pp) : "f"(pv));
                asm volatile("fma.rn.f32x2 %0, %1, %2, %0;" : "+l"(acc2[k][0]) : "l"(pp), "l"(g0));
                asm volatile("fma.rn.f32x2 %0, %1, %2, %0;" : "+l"(acc2[k][1]) : "l"(pp), "l"(g1));
                asm volatile("fma.rn.f32x2 %0, %1, %2, %0;" : "+l"(acc2[k][2]) : "l"(pp), "l"(g2));
                asm volatile("fma.rn.f32x2 %0, %1, %2, %0;" : "+l"(acc2[k][3]) : "l"(pp), "l"(g3));
                asm volatile("fma.rn.f32x2 %0, %1, %2, %0;" : "+l"(acc2[k][4]) : "l"(pp), "l"(g4));
                asm volatile("fma.rn.f32x2 %0, %1, %2, %0;" : "+l"(acc2[k][5]) : "l"(pp), "l"(g5));
                asm volatile("fma.rn.f32x2 %0, %1, %2, %0;" : "+l"(acc2[k][6]) : "l"(pp), "l"(g6));
                asm volatile("fma.rn.f32x2 %0, %1, %2, %0;" : "+l"(acc2[k][7]) : "l"(pp), "l"(g7));
            }
        }
    }

    // ---- epilogue: relu + both weighted reductions, per pixel ----
    float out_acc[NF];
#pragma unroll
    for (int f = 0; f < NF; f++) out_acc[f] = 0.f;

#pragma unroll
    for (int k = 0; k < 4; k++) {
        const int pq = t + 256 * k;
        const float w = s_W[pq];
        const float m = s_M[pq];
#pragma unroll
        for (int j = 0; j < 8; j++) {
            float s_lo, s_hi;
            asm volatile("mov.b64 {%0, %1}, %2;" : "=f"(s_lo), "=f"(s_hi) : "l"(acc2[k][j]));
            const float x_lo = s_pad[(2 * j)     * PSTR + cbase[k]];
            const float x_hi = s_pad[(2 * j + 1) * PSTR + cbase[k]];
            out_acc[2 * j]     += m * x_lo - w * fmaxf(x_lo - s_lo, 0.f);
            out_acc[2 * j + 1] += m * x_hi - w * fmaxf(x_hi - s_hi, 0.f);
        }
    }

    // ---- reduce over 256 threads ----
#pragma unroll
    for (int off = 16; off >= 1; off >>= 1) {
#pragma unroll
        for (int f = 0; f < NF; f++)
            out_acc[f] += __shfl_xor_sync(0xffffffffu, out_acc[f], off);
    }
    const int wid  = t >> 5;
    const int lane = t & 31;
    if (lane == 0) {
#pragma unroll
        for (int f = 0; f < NF; f++) s_red[wid * NF + f] = out_acc[f];
    }
    __syncthreads();
    if (t < NF) {
        float v = 0.f;
#pragma unroll
        for (int wv = 0; wv < 8; wv++) v += s_red[wv * NF + t];
        gout[((size_t)b * HW + ij) * NF + t] = v;
    }
}

extern "C" void kernel_launch(void* const* d_in, const int* in_sizes, int n_in,
                              void* d_out, int out_size)
{
    const float* inputs = (const float*)d_in[0];
    const float* M      = (const float*)d_in[1];
    const float* Wp     = (const float*)d_in[2];
    const float* G      = (const float*)d_in[3];
    float* out = (float*)d_out;

    const size_t smem = (size_t)(NC * PSTR + 2304 + 1024 + 1024 + 128) * sizeof(float);
    cudaFuncSetAttribute(inrf_kernel, cudaFuncAttributeMaxDynamicSharedMemorySize, (int)smem);

    dim3 grid(HW, 4);
    inrf_kernel<<<grid, 256, smem>>>(inputs, M, Wp, G, out);
}

// round 4
// speedup vs baseline: 2.5469x; 1.4751x over previous
#include <cuda_runtime.h>
#include <cuda_bf16.h>
#include <cstdint>

// INRF via mma.sync bf16 3-term split GEMM (base ISA — no tcgen05 on this toolchain).
// Per CTA: 8 ij (N=128), b-pair; 16 row-tiles of 128 pq.
// A[128x288] = [x_hi(144)|x_lo(144)] bf16, B[128x288] = [G_hi|G_lo] bf16.
// D = Ah@Gh + Al@Gh + Ah@Gl (fp32), fused epilogue:
//   out[b,ij,f] = sum_pq M2[ij,pq]*x[pq,f] - W2[ij,pq]*relu(x[pq,f]-D[pq,(ij,f)]).

#define STRE 296            // A/B row stride, bf16 elements (conflict-free ldmatrix)
#define STRB (STRE * 2)     // 592 bytes
#define XSTR 20             // x-plane row stride, floats (conflict-free)

#define SM_A   0            // 128 * 592 = 75776
#define SM_B   75776        // 75776
#define SM_M2  151552       // 8*1024*4 = 32768
#define SM_W2  184320       // 32768
#define SM_X   217088       // 128*20*4 = 10240
#define SM_TOT 227328

__device__ __forceinline__ void ldsm_x4(uint32_t r[4], uint32_t addr) {
    asm volatile("ldmatrix.sync.aligned.m8n8.x4.shared.b16 {%0,%1,%2,%3}, [%4];"
                 : "=r"(r[0]), "=r"(r[1]), "=r"(r[2]), "=r"(r[3]) : "r"(addr));
}
__device__ __forceinline__ void ldsm_x2(uint32_t r[2], uint32_t addr) {
    asm volatile("ldmatrix.sync.aligned.m8n8.x2.shared.b16 {%0,%1}, [%2];"
                 : "=r"(r[0]), "=r"(r[1]) : "r"(addr));
}
__device__ __forceinline__ void mma_bf16(float d[4], const uint32_t a[4],
                                         const uint32_t b[2]) {
    asm volatile("mma.sync.aligned.m16n8k16.row.col.f32.bf16.bf16.f32 "
                 "{%0,%1,%2,%3}, {%4,%5,%6,%7}, {%8,%9}, {%0,%1,%2,%3};"
                 : "+f"(d[0]), "+f"(d[1]), "+f"(d[2]), "+f"(d[3])
                 : "r"(a[0]), "r"(a[1]), "r"(a[2]), "r"(a[3]),
                   "r"(b[0]), "r"(b[1]));
}

// 8 floats -> packed hi bf16x8 (H) and lo bf16x8 (L)
__device__ __forceinline__ void cvt_hilo8(float4 a, float4 b, uint4& H, uint4& L) {
    float xs[8] = {a.x, a.y, a.z, a.w, b.x, b.y, b.z, b.w};
    uint32_t h[4], l[4];
#pragma unroll
    for (int i = 0; i < 4; i++) {
        __nv_bfloat16 h0 = __float2bfloat16_rn(xs[2 * i]);
        __nv_bfloat16 h1 = __float2bfloat16_rn(xs[2 * i + 1]);
        __nv_bfloat16 l0 = __float2bfloat16_rn(xs[2 * i]     - __bfloat162float(h0));
        __nv_bfloat16 l1 = __float2bfloat16_rn(xs[2 * i + 1] - __bfloat162float(h1));
        __nv_bfloat162 hp = __halves2bfloat162(h0, h1);
        __nv_bfloat162 lp = __halves2bfloat162(l0, l1);
        h[i] = *reinterpret_cast<uint32_t*>(&hp);
        l[i] = *reinterpret_cast<uint32_t*>(&lp);
    }
    H = make_uint4(h[0], h[1], h[2], h[3]);
    L = make_uint4(l[0], l[1], l[2], l[3]);
}

__global__ __launch_bounds__(256, 1)
void inrf_hmma(const float* __restrict__ gin, const float* __restrict__ gM,
               const float* __restrict__ gW, const float* __restrict__ gG,
               float* __restrict__ gout)
{
    extern __shared__ char smem[];
    const int tid  = threadIdx.x;
    const int wid  = tid >> 5;
    const int lane = tid & 31;
    const int ij0  = blockIdx.x * 8;
    const int by   = blockIdx.y;

    float* sm2 = (float*)(smem + SM_M2);
    float* sw2 = (float*)(smem + SM_W2);
    float* sx  = (float*)(smem + SM_X);

    // ---- stage M2/W2 [8 ij][1024 pq] (fp32, vectorized) ----
    {
        const float4* gm4 = (const float4*)(gM + (size_t)ij0 * 1024);
        const float4* gw4 = (const float4*)(gW + (size_t)ij0 * 1024);
        float4* m4 = (float4*)sm2;
        float4* w4 = (float4*)sw2;
        for (int i = tid; i < 2048; i += 256) { m4[i] = gm4[i]; w4[i] = gw4[i]; }
    }
    // ---- build B[128 x 288] once: row n=(ijl,f), k = tap*16+c (hi), 144+ (lo) ----
    {
        const int row  = tid >> 1;
        const int half = tid & 1;
        const int ijl  = row >> 4, f = row & 15;
        const float* gb = gG + (size_t)(ij0 + ijl) * 2304 + f;
        char* brow = smem + SM_B + row * STRB;
        const int t0 = half ? 5 : 0, t1 = half ? 9 : 5;
        for (int tap = t0; tap < t1; tap++) {
            float xs[16];
#pragma unroll
            for (int c = 0; c < 16; c++) xs[c] = gb[(tap * 16 + c) * 16];
            uint4 H0, L0, H1, L1;
            cvt_hilo8(make_float4(xs[0], xs[1], xs[2], xs[3]),
                      make_float4(xs[4], xs[5], xs[6], xs[7]), H0, L0);
            cvt_hilo8(make_float4(xs[8], xs[9], xs[10], xs[11]),
                      make_float4(xs[12], xs[13], xs[14], xs[15]), H1, L1);
            *(uint4*)(brow + (tap * 16) * 2)            = H0;
            *(uint4*)(brow + (tap * 16) * 2 + 16)       = H1;
            *(uint4*)(brow + (144 + tap * 16) * 2)      = L0;
            *(uint4*)(brow + (144 + tap * 16) * 2 + 16) = L1;
        }
    }

    const uint32_t sbase = (uint32_t)__cvta_generic_to_shared(smem);
    // ldmatrix lane bases (canonical m16n8k16 mappings)
    const uint32_t aL = sbase + SM_A + (lane & 15) * STRB + (lane >> 4) * 16;
    const uint32_t bL = sbase + SM_B + (wid * 16 + (lane & 7)) * STRB
                        + ((lane >> 3) & 1) * 16;

    float acc_f[4] = {0.f, 0.f, 0.f, 0.f};

#pragma unroll 1
    for (int t = 0; t < 16; t++) {
        const int b   = by * 2 + (t >> 3);
        const int pqb = (t & 7) * 128;

        __syncthreads();   // previous tile's readers done

        // ---- build A tile (+ exact fp32 x plane at tap 4) ----
        {
            const int row = tid >> 1, half = tid & 1;
            const int pq = pqb + row;
            const int p = pq >> 5, q = pq & 31;
            const float* src = gin + (size_t)b * 16384;
            char* arow = smem + SM_A + row * STRB;
            const int t0 = half ? 4 : 0, t1 = half ? 9 : 4;
#pragma unroll
            for (int tap = t0; tap < t1; tap++) {
                const int pp = p + tap / 3 - 1, qq = q + tap % 3 - 1;
                float4 a0, a1, a2, a3;
                if ((unsigned)pp < 32u && (unsigned)qq < 32u) {
                    const float4* s4 = (const float4*)(src + (pp * 32 + qq) * 16);
                    a0 = s4[0]; a1 = s4[1]; a2 = s4[2]; a3 = s4[3];
                } else {
                    a0 = a1 = a2 = a3 = make_float4(0.f, 0.f, 0.f, 0.f);
                }
                if (tap == 4) {   // center: exact x plane
                    float4* xp = (float4*)(sx + row * XSTR);
                    xp[0] = a0; xp[1] = a1; xp[2] = a2; xp[3] = a3;
                }
                uint4 H0, L0, H1, L1;
                cvt_hilo8(a0, a1, H0, L0);
                cvt_hilo8(a2, a3, H1, L1);
                *(uint4*)(arow + (tap * 16) * 2)            = H0;
                *(uint4*)(arow + (tap * 16) * 2 + 16)       = H1;
                *(uint4*)(arow + (144 + tap * 16) * 2)      = L0;
                *(uint4*)(arow + (144 + tap * 16) * 2 + 16) = L1;
            }
        }
        __syncthreads();   // A + x ready

        // ---- 27 K-steps of m16n8k16 ----
        float d[8][2][4];
#pragma unroll
        for (int mt = 0; mt < 8; mt++)
#pragma unroll
            for (int nt = 0; nt < 2; nt++)
#pragma unroll
                for (int r = 0; r < 4; r++) d[mt][nt][r] = 0.f;

#pragma unroll
        for (int term = 0; term < 3; term++) {
#pragma unroll 1
            for (int s = 0; s < 9; s++) {
                const int ka = ((term == 1) ? 144 : 0) + s * 16;
                const int kb = ((term == 2) ? 144 : 0) + s * 16;
                uint32_t b0[2], b1[2];
                ldsm_x2(b0, bL + kb * 2);
                ldsm_x2(b1, bL + 8 * STRB + kb * 2);
#pragma unroll
                for (int mt = 0; mt < 8; mt++) {
                    uint32_t a[4];
                    ldsm_x4(a, aL + mt * 16 * STRB + ka * 2);
                    mma_bf16(d[mt][0], a, b0);
                    mma_bf16(d[mt][1], a, b1);
                }
            }
        }

        // ---- fused epilogue from fragments ----
        {
            const int rl = lane >> 2;
            const float* m2w = sm2 + wid * 1024;
            const float* w2w = sw2 + wid * 1024;
#pragma unroll
            for (int mt = 0; mt < 8; mt++) {
                const int r0 = pqb + mt * 16 + rl;
                const float m2a = m2w[r0],     w2a = w2w[r0];
                const float m2b = m2w[r0 + 8], w2b = w2w[r0 + 8];
                const int rrbase = mt * 16 + rl;
#pragma unroll
                for (int nt = 0; nt < 2; nt++)
#pragma unroll
                    for (int reg = 0; reg < 4; reg++) {
                        const int rr = rrbase + ((reg >> 1) & 1) * 8;
                        const int f  = nt * 8 + 2 * (lane & 3) + (reg & 1);
                        const float x  = sx[rr * XSTR + f];
                        const float sv = d[mt][nt][reg];
                        const float m2 = (reg < 2) ? m2a : m2b;
                        const float w2 = (reg < 2) ? w2a : w2b;
                        acc_f[nt * 2 + (reg & 1)] +=
                            m2 * x - w2 * fmaxf(x - sv, 0.f);
                    }
            }
        }

        // ---- flush per b ----
        if ((t & 7) == 7) {
#pragma unroll
            for (int off = 4; off <= 16; off <<= 1)
#pragma unroll
                for (int j = 0; j < 4; j++)
                    acc_f[j] += __shfl_xor_sync(0xffffffffu, acc_f[j], off);
            if (lane < 4) {
                const int ij = ij0 + wid;
                float* op = gout + ((size_t)b * 1024 + ij) * 16;
#pragma unroll
                for (int nt = 0; nt < 2; nt++)
#pragma unroll
                    for (int par = 0; par < 2; par++)
                        op[nt * 8 + 2 * lane + par] = acc_f[nt * 2 + par];
            }
#pragma unroll
            for (int j = 0; j < 4; j++) acc_f[j] = 0.f;
        }
    }
}

extern "C" void kernel_launch(void* const* d_in, const int* in_sizes, int n_in,
                              void* d_out, int out_size)
{
    const float* inputs = (const float*)d_in[0];
    const float* M      = (const float*)d_in[1];
    const float* Wp     = (const float*)d_in[2];
    const float* G      = (const float*)d_in[3];
    float* out = (float*)d_out;

    cudaFuncSetAttribute(inrf_hmma, cudaFuncAttributeMaxDynamicSharedMemorySize, SM_TOT);
    dim3 grid(128, 2);
    inrf_hmma<<<grid, 256, SM_TOT>>>(inputs, M, Wp, G, out);
}

// round 5
// speedup vs baseline: 2.6305x; 1.0328x over previous
#include <cuda_runtime.h>
#include <cuda_bf16.h>
#include <cstdint>

// INRF via mma.sync bf16 3-term split GEMM — round 5:
// B fragments preloaded to registers (tile-invariant), A-hi fragments reused
// across terms: per k-step, 16 ldsm_x4 feed 48 MMAs (was 30 ldmatrix).

#define STRE 296            // A/B row stride, bf16 elements (conflict-free ldmatrix)
#define STRB (STRE * 2)     // 592 bytes
#define XSTR 20             // x-plane row stride, floats

#define SM_A   0            // 128 * 592 = 75776
#define SM_B   75776        // 75776
#define SM_M2  151552       // 32768
#define SM_W2  184320       // 32768
#define SM_X   217088       // 10240
#define SM_TOT 227328

__device__ __forceinline__ void ldsm_x4(uint32_t r[4], uint32_t addr) {
    asm volatile("ldmatrix.sync.aligned.m8n8.x4.shared.b16 {%0,%1,%2,%3}, [%4];"
                 : "=r"(r[0]), "=r"(r[1]), "=r"(r[2]), "=r"(r[3]) : "r"(addr));
}
__device__ __forceinline__ void mma_bf16(float d[4], const uint32_t a[4],
                                         const uint32_t b[2]) {
    asm volatile("mma.sync.aligned.m16n8k16.row.col.f32.bf16.bf16.f32 "
                 "{%0,%1,%2,%3}, {%4,%5,%6,%7}, {%8,%9}, {%0,%1,%2,%3};"
                 : "+f"(d[0]), "+f"(d[1]), "+f"(d[2]), "+f"(d[3])
                 : "r"(a[0]), "r"(a[1]), "r"(a[2]), "r"(a[3]),
                   "r"(b[0]), "r"(b[1]));
}

__device__ __forceinline__ void cvt_hilo8(float4 a, float4 b, uint4& H, uint4& L) {
    float xs[8] = {a.x, a.y, a.z, a.w, b.x, b.y, b.z, b.w};
    uint32_t h[4], l[4];
#pragma unroll
    for (int i = 0; i < 4; i++) {
        __nv_bfloat16 h0 = __float2bfloat16_rn(xs[2 * i]);
        __nv_bfloat16 h1 = __float2bfloat16_rn(xs[2 * i + 1]);
        __nv_bfloat16 l0 = __float2bfloat16_rn(xs[2 * i]     - __bfloat162float(h0));
        __nv_bfloat16 l1 = __float2bfloat16_rn(xs[2 * i + 1] - __bfloat162float(h1));
        __nv_bfloat162 hp = __halves2bfloat162(h0, h1);
        __nv_bfloat162 lp = __halves2bfloat162(l0, l1);
        h[i] = *reinterpret_cast<uint32_t*>(&hp);
        l[i] = *reinterpret_cast<uint32_t*>(&lp);
    }
    H = make_uint4(h[0], h[1], h[2], h[3]);
    L = make_uint4(l[0], l[1], l[2], l[3]);
}

__global__ __launch_bounds__(256, 1)
void inrf_hmma(const float* __restrict__ gin, const float* __restrict__ gM,
               const float* __restrict__ gW, const float* __restrict__ gG,
               float* __restrict__ gout)
{
    extern __shared__ char smem[];
    const int tid  = threadIdx.x;
    const int wid  = tid >> 5;
    const int lane = tid & 31;
    const int ij0  = blockIdx.x * 8;
    const int by   = blockIdx.y;

    float* sm2 = (float*)(smem + SM_M2);
    float* sw2 = (float*)(smem + SM_W2);
    float* sx  = (float*)(smem + SM_X);

    // ---- stage M2/W2 ----
    {
        const float4* gm4 = (const float4*)(gM + (size_t)ij0 * 1024);
        const float4* gw4 = (const float4*)(gW + (size_t)ij0 * 1024);
        float4* m4 = (float4*)sm2;
        float4* w4 = (float4*)sw2;
        for (int i = tid; i < 2048; i += 256) { m4[i] = gm4[i]; w4[i] = gw4[i]; }
    }
    // ---- build B[128 x 288] once ----
    {
        const int row  = tid >> 1;
        const int half = tid & 1;
        const int ijl  = row >> 4, f = row & 15;
        const float* gb = gG + (size_t)(ij0 + ijl) * 2304 + f;
        char* brow = smem + SM_B + row * STRB;
        const int t0 = half ? 5 : 0, t1 = half ? 9 : 5;
        for (int tap = t0; tap < t1; tap++) {
            float xs[16];
#pragma unroll
            for (int c = 0; c < 16; c++) xs[c] = gb[(tap * 16 + c) * 16];
            uint4 H0, L0, H1, L1;
            cvt_hilo8(make_float4(xs[0], xs[1], xs[2], xs[3]),
                      make_float4(xs[4], xs[5], xs[6], xs[7]), H0, L0);
            cvt_hilo8(make_float4(xs[8], xs[9], xs[10], xs[11]),
                      make_float4(xs[12], xs[13], xs[14], xs[15]), H1, L1);
            *(uint4*)(brow + (tap * 16) * 2)            = H0;
            *(uint4*)(brow + (tap * 16) * 2 + 16)       = H1;
            *(uint4*)(brow + (144 + tap * 16) * 2)      = L0;
            *(uint4*)(brow + (144 + tap * 16) * 2 + 16) = L1;
        }
    }
    __syncthreads();

    const uint32_t sbase = (uint32_t)__cvta_generic_to_shared(smem);
    const uint32_t aL = sbase + SM_A + (lane & 15) * STRB + (lane >> 4) * 16;
    // x4 B address: matrices (nt0/k0, nt0/k1, nt1/k0, nt1/k1)
    const uint32_t bL4 = sbase + SM_B +
        (wid * 16 + (lane & 7) + ((lane >> 4) << 3)) * STRB + (((lane >> 3) & 1) << 4);

    // ---- preload ALL B fragments (tile-invariant): 9 steps x (hi,lo) x4 ----
    uint32_t bh[9][4], bl[9][4];
#pragma unroll
    for (int s = 0; s < 9; s++) {
        ldsm_x4(bh[s], bL4 + (s * 16) * 2);
        ldsm_x4(bl[s], bL4 + (144 + s * 16) * 2);
    }

    float acc_f[4] = {0.f, 0.f, 0.f, 0.f};

#pragma unroll 1
    for (int t = 0; t < 16; t++) {
        const int b   = by * 2 + (t >> 3);
        const int pqb = (t & 7) * 128;

        __syncthreads();   // previous tile's readers done

        // ---- build A tile (+ exact fp32 x plane at tap 4) ----
        {
            const int row = tid >> 1, half = tid & 1;
            const int pq = pqb + row;
            const int p = pq >> 5, q = pq & 31;
            const float* src = gin + (size_t)b * 16384;
            char* arow = smem + SM_A + row * STRB;
            const int t0 = half ? 4 : 0, t1 = half ? 9 : 4;
#pragma unroll
            for (int tap = t0; tap < t1; tap++) {
                const int pp = p + tap / 3 - 1, qq = q + tap % 3 - 1;
                float4 a0, a1, a2, a3;
                if ((unsigned)pp < 32u && (unsigned)qq < 32u) {
                    const float4* s4 = (const float4*)(src + (pp * 32 + qq) * 16);
                    a0 = s4[0]; a1 = s4[1]; a2 = s4[2]; a3 = s4[3];
                } else {
                    a0 = a1 = a2 = a3 = make_float4(0.f, 0.f, 0.f, 0.f);
                }
                if (tap == 4) {
                    float4* xp = (float4*)(sx + row * XSTR);
                    xp[0] = a0; xp[1] = a1; xp[2] = a2; xp[3] = a3;
                }
                uint4 H0, L0, H1, L1;
                cvt_hilo8(a0, a1, H0, L0);
                cvt_hilo8(a2, a3, H1, L1);
                *(uint4*)(arow + (tap * 16) * 2)            = H0;
                *(uint4*)(arow + (tap * 16) * 2 + 16)       = H1;
                *(uint4*)(arow + (144 + tap * 16) * 2)      = L0;
                *(uint4*)(arow + (144 + tap * 16) * 2 + 16) = L1;
            }
        }
        __syncthreads();   // A + x ready

        // ---- 9 k-steps; per step: a_hi reused for Gh and Gl, a_lo for Gh ----
        float d[8][2][4];
#pragma unroll
        for (int mt = 0; mt < 8; mt++)
#pragma unroll
            for (int nt = 0; nt < 2; nt++)
#pragma unroll
                for (int r = 0; r < 4; r++) d[mt][nt][r] = 0.f;

#pragma unroll 1
        for (int s = 0; s < 9; s++) {
            const int ka_hi = s * 16;
            const int ka_lo = 144 + s * 16;
#pragma unroll
            for (int mt = 0; mt < 8; mt++) {
                uint32_t a[4];
                ldsm_x4(a, aL + mt * 16 * STRB + ka_hi * 2);
                mma_bf16(d[mt][0], a, &bh[s][0]);
                mma_bf16(d[mt][1], a, &bh[s][2]);
                mma_bf16(d[mt][0], a, &bl[s][0]);
                mma_bf16(d[mt][1], a, &bl[s][2]);
            }
#pragma unroll
            for (int mt = 0; mt < 8; mt++) {
                uint32_t a[4];
                ldsm_x4(a, aL + mt * 16 * STRB + ka_lo * 2);
                mma_bf16(d[mt][0], a, &bh[s][0]);
                mma_bf16(d[mt][1], a, &bh[s][2]);
            }
        }

        // ---- fused epilogue from fragments ----
        {
            const int rl = lane >> 2;
            const float* m2w = sm2 + wid * 1024;
            const float* w2w = sw2 + wid * 1024;
#pragma unroll
            for (int mt = 0; mt < 8; mt++) {
                const int r0 = pqb + mt * 16 + rl;
                const float m2a = m2w[r0],     w2a = w2w[r0];
                const float m2b = m2w[r0 + 8], w2b = w2w[r0 + 8];
                const int rrbase = mt * 16 + rl;
#pragma unroll
                for (int nt = 0; nt < 2; nt++)
#pragma unroll
                    for (int reg = 0; reg < 4; reg++) {
                        const int rr = rrbase + ((reg >> 1) & 1) * 8;
                        const int f  = nt * 8 + 2 * (lane & 3) + (reg & 1);
                        const float x  = sx[rr * XSTR + f];
                        const float sv = d[mt][nt][reg];
                        const float m2 = (reg < 2) ? m2a : m2b;
                        const float w2 = (reg < 2) ? w2a : w2b;
                        acc_f[nt * 2 + (reg & 1)] +=
                            m2 * x - w2 * fmaxf(x - sv, 0.f);
                    }
            }
        }

        // ---- flush per b ----
        if ((t & 7) == 7) {
#pragma unroll
            for (int off = 4; off <= 16; off <<= 1)
#pragma unroll
                for (int j = 0; j < 4; j++)
                    acc_f[j] += __shfl_xor_sync(0xffffffffu, acc_f[j], off);
            if (lane < 4) {
                const int ij = ij0 + wid;
                float* op = gout + ((size_t)b * 1024 + ij) * 16;
#pragma unroll
                for (int nt = 0; nt < 2; nt++)
#pragma unroll
                    for (int par = 0; par < 2; par++)
                        op[nt * 8 + 2 * lane + par] = acc_f[nt * 2 + par];
            }
#pragma unroll
            for (int j = 0; j < 4; j++) acc_f[j] = 0.f;
        }
    }
}

extern "C" void kernel_launch(void* const* d_in, const int* in_sizes, int n_in,
                              void* d_out, int out_size)
{
    const float* inputs = (const float*)d_in[0];
    const float* M      = (const float*)d_in[1];
    const float* Wp     = (const float*)d_in[2];
    const float* G      = (const float*)d_in[3];
    float* out = (float*)d_out;

    cudaFuncSetAttribute(inrf_hmma, cudaFuncAttributeMaxDynamicSharedMemorySize, SM_TOT);
    dim3 grid(128, 2);
    inrf_hmma<<<grid, 256, SM_TOT>>>(inputs, M, Wp, G, out);
}

// round 6
// speedup vs baseline: 3.2013x; 1.2170x over previous
#include <cuda_runtime.h>
#include <cuda_bf16.h>
#include <cstdint>

// INRF — round 6: precomputed im2col scratch (kernel 1) + cp.async
// double-buffered HMMA mainloop (kernel 2). A tiles are identical across all
// ij-group CTAs, so build them ONCE in gmem as the exact smem image and
// stream them with LDGSTS; mainloop = pure ldsm+MMA+epilogue.

#define STRE 296
#define STRB (STRE * 2)          // 592 B A/B row stride
#define TILE_BYTES (128 * STRB)  // 75776
#define XSTR 20                  // x-plane row stride (floats), conflict-free

#define SM_A0  0
#define SM_A1  TILE_BYTES        // 75776
#define SM_X0  (2 * TILE_BYTES)  // 151552
#define SM_X1  (SM_X0 + 128 * XSTR * 4)   // +10240
#define SM_TOT (SM_X1 + 128 * XSTR * 4)   // 172032

__device__ __align__(16) unsigned char g_scratch[32 * TILE_BYTES];

__device__ __forceinline__ void ldsm_x4(uint32_t r[4], uint32_t addr) {
    asm volatile("ldmatrix.sync.aligned.m8n8.x4.shared.b16 {%0,%1,%2,%3}, [%4];"
                 : "=r"(r[0]), "=r"(r[1]), "=r"(r[2]), "=r"(r[3]) : "r"(addr));
}
__device__ __forceinline__ void mma_bf16(float d[4], const uint32_t a[4],
                                         const uint32_t b[2]) {
    asm volatile("mma.sync.aligned.m16n8k16.row.col.f32.bf16.bf16.f32 "
                 "{%0,%1,%2,%3}, {%4,%5,%6,%7}, {%8,%9}, {%0,%1,%2,%3};"
                 : "+f"(d[0]), "+f"(d[1]), "+f"(d[2]), "+f"(d[3])
                 : "r"(a[0]), "r"(a[1]), "r"(a[2]), "r"(a[3]),
                   "r"(b[0]), "r"(b[1]));
}
__device__ __forceinline__ void cp16(uint32_t dst, const void* src) {
    asm volatile("cp.async.ca.shared.global [%0], [%1], 16;"
                 :: "r"(dst), "l"(src) : "memory");
}
#define CP_COMMIT() asm volatile("cp.async.commit_group;" ::: "memory")
#define CP_WAIT0()  asm volatile("cp.async.wait_group 0;" ::: "memory")

__device__ __forceinline__ void cvt_hilo8(float4 a, float4 b, uint4& H, uint4& L) {
    float xs[8] = {a.x, a.y, a.z, a.w, b.x, b.y, b.z, b.w};
    uint32_t h[4], l[4];
#pragma unroll
    for (int i = 0; i < 4; i++) {
        __nv_bfloat16 h0 = __float2bfloat16_rn(xs[2 * i]);
        __nv_bfloat16 h1 = __float2bfloat16_rn(xs[2 * i + 1]);
        __nv_bfloat16 l0 = __float2bfloat16_rn(xs[2 * i]     - __bfloat162float(h0));
        __nv_bfloat16 l1 = __float2bfloat16_rn(xs[2 * i + 1] - __bfloat162float(h1));
        __nv_bfloat162 hp = __halves2bfloat162(h0, h1);
        __nv_bfloat162 lp = __halves2bfloat162(l0, l1);
        h[i] = *reinterpret_cast<uint32_t*>(&hp);
        l[i] = *reinterpret_cast<uint32_t*>(&lp);
    }
    H = make_uint4(h[0], h[1], h[2], h[3]);
    L = make_uint4(l[0], l[1], l[2], l[3]);
}

// ---- kernel 1: im2col + hi/lo split, smem-image layout ----
__global__ __launch_bounds__(256)
void im2col_prep(const float* __restrict__ gin)
{
    const int tile = blockIdx.x;          // b*8 + tl
    const int b = tile >> 3, tl = tile & 7;
    const int row = threadIdx.x >> 1, half = threadIdx.x & 1;
    const int pq = tl * 128 + row;
    const int p = pq >> 5, q = pq & 31;
    const float* src = gin + (size_t)b * 16384;
    unsigned char* arow = g_scratch + (size_t)tile * TILE_BYTES + row * STRB;
    const int t0 = half ? 4 : 0, t1 = half ? 9 : 4;
#pragma unroll
    for (int tap = t0; tap < t1; tap++) {
        const int pp = p + tap / 3 - 1, qq = q + tap % 3 - 1;
        float4 a0, a1, a2, a3;
        if ((unsigned)pp < 32u && (unsigned)qq < 32u) {
            const float4* s4 = (const float4*)(src + (pp * 32 + qq) * 16);
            a0 = s4[0]; a1 = s4[1]; a2 = s4[2]; a3 = s4[3];
        } else {
            a0 = a1 = a2 = a3 = make_float4(0.f, 0.f, 0.f, 0.f);
        }
        uint4 H0, L0, H1, L1;
        cvt_hilo8(a0, a1, H0, L0);
        cvt_hilo8(a2, a3, H1, L1);
        *(uint4*)(arow + (tap * 16) * 2)            = H0;
        *(uint4*)(arow + (tap * 16) * 2 + 16)       = H1;
        *(uint4*)(arow + (144 + tap * 16) * 2)      = L0;
        *(uint4*)(arow + (144 + tap * 16) * 2 + 16) = L1;
    }
}

// ---- kernel 2: mainloop ----
__global__ __launch_bounds__(256, 1)
void inrf_hmma(const float* __restrict__ gin, const float* __restrict__ gM,
               const float* __restrict__ gW, const float* __restrict__ gG,
               float* __restrict__ gout)
{
    extern __shared__ char smem[];
    const int tid  = threadIdx.x;
    const int wid  = tid >> 5;
    const int lane = tid & 31;
    const int ij0  = blockIdx.x * 8;
    const int by   = blockIdx.y;
    const uint32_t sbase = (uint32_t)__cvta_generic_to_shared(smem);

    // ---- build B[128x288] into A-buf0 region (temporary), preload to regs ----
    {
        const int row  = tid >> 1;
        const int half = tid & 1;
        const int ijl  = row >> 4, f = row & 15;
        const float* gb = gG + (size_t)(ij0 + ijl) * 2304 + f;
        char* brow = smem + SM_A0 + row * STRB;
        const int t0 = half ? 5 : 0, t1 = half ? 9 : 5;
        for (int tap = t0; tap < t1; tap++) {
            float xs[16];
#pragma unroll
            for (int c = 0; c < 16; c++) xs[c] = gb[(tap * 16 + c) * 16];
            uint4 H0, L0, H1, L1;
            cvt_hilo8(make_float4(xs[0], xs[1], xs[2], xs[3]),
                      make_float4(xs[4], xs[5], xs[6], xs[7]), H0, L0);
            cvt_hilo8(make_float4(xs[8], xs[9], xs[10], xs[11]),
                      make_float4(xs[12], xs[13], xs[14], xs[15]), H1, L1);
            *(uint4*)(brow + (tap * 16) * 2)            = H0;
            *(uint4*)(brow + (tap * 16) * 2 + 16)       = H1;
            *(uint4*)(brow + (144 + tap * 16) * 2)      = L0;
            *(uint4*)(brow + (144 + tap * 16) * 2 + 16) = L1;
        }
    }
    __syncthreads();

    uint32_t bh[9][4], bl[9][4];
    {
        const uint32_t bL4 = sbase + SM_A0 +
            (wid * 16 + (lane & 7) + ((lane >> 4) << 3)) * STRB +
            (((lane >> 3) & 1) << 4);
#pragma unroll
        for (int s = 0; s < 9; s++) {
            ldsm_x4(bh[s], bL4 + (s * 16) * 2);
            ldsm_x4(bl[s], bL4 + (144 + s * 16) * 2);
        }
    }
    __syncthreads();   // B region free -> becomes A buf0

    // ---- prefetch tile 0 ----
    {
        const int b = by * 2, tl = 0;
        const unsigned char* asrc = g_scratch + (size_t)(b * 8 + tl) * TILE_BYTES;
        for (int i = tid; i < TILE_BYTES / 16; i += 256)
            cp16(sbase + SM_A0 + i * 16, asrc + i * 16);
        const char* xsrc = (const char*)(gin + (size_t)b * 16384);
        for (int i = tid; i < 512; i += 256)
            cp16(sbase + SM_X0 + (i >> 2) * (XSTR * 4) + (i & 3) * 16, xsrc + i * 16);
        CP_COMMIT();
        CP_WAIT0();
    }
    __syncthreads();

    const uint32_t aL = sbase + (lane & 15) * STRB + (lane >> 4) * 16;
    const float* m2w = gM + (size_t)(ij0 + wid) * 1024;
    const float* w2w = gW + (size_t)(ij0 + wid) * 1024;

    float acc_f[4] = {0.f, 0.f, 0.f, 0.f};

#pragma unroll 1
    for (int t = 0; t < 16; t++) {
        const int b   = by * 2 + (t >> 3);
        const int pqb = (t & 7) * 128;
        const uint32_t abuf = (t & 1) ? SM_A1 : SM_A0;
        const uint32_t xbuf = (t & 1) ? SM_X1 : SM_X0;

        // ---- prefetch tile t+1 into the other buffer ----
        if (t < 15) {
            const int tn = t + 1;
            const int bn = by * 2 + (tn >> 3);
            const uint32_t abn = (tn & 1) ? SM_A1 : SM_A0;
            const uint32_t xbn = (tn & 1) ? SM_X1 : SM_X0;
            const unsigned char* asrc =
                g_scratch + (size_t)(bn * 8 + (tn & 7)) * TILE_BYTES;
            for (int i = tid; i < TILE_BYTES / 16; i += 256)
                cp16(sbase + abn + i * 16, asrc + i * 16);
            const char* xsrc =
                (const char*)(gin + ((size_t)bn * 1024 + (tn & 7) * 128) * 16);
            for (int i = tid; i < 512; i += 256)
                cp16(sbase + xbn + (i >> 2) * (XSTR * 4) + (i & 3) * 16,
                     xsrc + i * 16);
            CP_COMMIT();
        }

        // ---- 9 k-steps: a_hi feeds Gh+Gl, a_lo feeds Gh ----
        float d[8][2][4];
#pragma unroll
        for (int mt = 0; mt < 8; mt++)
#pragma unroll
            for (int nt = 0; nt < 2; nt++)
#pragma unroll
                for (int r = 0; r < 4; r++) d[mt][nt][r] = 0.f;

#pragma unroll 1
        for (int s = 0; s < 9; s++) {
            const uint32_t base_hi = aL + abuf + (s * 16) * 2;
            const uint32_t base_lo = aL + abuf + ((144 + s * 16)) * 2;
#pragma unroll
            for (int mt = 0; mt < 8; mt++) {
                uint32_t a[4];
                ldsm_x4(a, base_hi + mt * 16 * STRB);
                mma_bf16(d[mt][0], a, &bh[s][0]);
                mma_bf16(d[mt][1], a, &bh[s][2]);
                mma_bf16(d[mt][0], a, &bl[s][0]);
                mma_bf16(d[mt][1], a, &bl[s][2]);
            }
#pragma unroll
            for (int mt = 0; mt < 8; mt++) {
                uint32_t a[4];
                ldsm_x4(a, base_lo + mt * 16 * STRB);
                mma_bf16(d[mt][0], a, &bh[s][0]);
                mma_bf16(d[mt][1], a, &bh[s][2]);
            }
        }

        // ---- fused epilogue ----
        {
            const float* sx = (const float*)(smem + xbuf);
            const int rl = lane >> 2;
#pragma unroll
            for (int mt = 0; mt < 8; mt++) {
                const int r0 = pqb + mt * 16 + rl;
                const float m2a = __ldg(m2w + r0),     w2a = __ldg(w2w + r0);
                const float m2b = __ldg(m2w + r0 + 8), w2b = __ldg(w2w + r0 + 8);
                const int rrbase = mt * 16 + rl;
#pragma unroll
                for (int nt = 0; nt < 2; nt++)
#pragma unroll
                    for (int reg = 0; reg < 4; reg++) {
                        const int rr = rrbase + ((reg >> 1) & 1) * 8;
                        const int f  = nt * 8 + 2 * (lane & 3) + (reg & 1);
                        const float x  = sx[rr * XSTR + f];
                        const float sv = d[mt][nt][reg];
                        const float m2 = (reg < 2) ? m2a : m2b;
                        const float w2 = (reg < 2) ? w2a : w2b;
                        acc_f[nt * 2 + (reg & 1)] +=
                            m2 * x - w2 * fmaxf(x - sv, 0.f);
                    }
            }
        }

        if (t < 15) CP_WAIT0();
        __syncthreads();

        // ---- flush per b ----
        if ((t & 7) == 7) {
#pragma unroll
            for (int off = 4; off <= 16; off <<= 1)
#pragma unroll
                for (int j = 0; j < 4; j++)
                    acc_f[j] += __shfl_xor_sync(0xffffffffu, acc_f[j], off);
            if (lane < 4) {
                const int ij = ij0 + wid;
                float* op = gout + ((size_t)b * 1024 + ij) * 16;
#pragma unroll
                for (int nt = 0; nt < 2; nt++)
#pragma unroll
                    for (int par = 0; par < 2; par++)
                        op[nt * 8 + 2 * lane + par] = acc_f[nt * 2 + par];
            }
#pragma unroll
            for (int j = 0; j < 4; j++) acc_f[j] = 0.f;
        }
    }
}

extern "C" void kernel_launch(void* const* d_in, const int* in_sizes, int n_in,
                              void* d_out, int out_size)
{
    const float* inputs = (const float*)d_in[0];
    const float* M      = (const float*)d_in[1];
    const float* Wp     = (const float*)d_in[2];
    const float* G      = (const float*)d_in[3];
    float* out = (float*)d_out;

    im2col_prep<<<32, 256>>>(inputs);

    cudaFuncSetAttribute(inrf_hmma, cudaFuncAttributeMaxDynamicSharedMemorySize, SM_TOT);
    dim3 grid(128, 2);
    inrf_hmma<<<grid, 256, SM_TOT>>>(inputs, M, Wp, G, out);
}

// round 10
// speedup vs baseline: 3.2237x; 1.0070x over previous
#include <cuda_runtime.h>
#include <cuda_bf16.h>
#include <cstdint>

// INRF — round 8: R7 design (2 CTAs/SM, m-tile 64, cp.async from im2col
// scratch) with B stride fixed to 304 B (16-aligned, conflict-free).

#define STRB 592                  // A row stride bytes (288 bf16 + pad)
#define BSTR 304                  // B row stride bytes (multiple of 16!)
#define CH   37888                // 64-row A chunk bytes
#define TILE_BYTES (128 * STRB)   // kernel1 tile (128 rows)

#define SM_A0  0
#define SM_A1  37888
#define SM_BLO 75776              // 128*304 = 38912 bytes
#define SM_TOT 114688             // 112 KB -> 2 CTAs/SM

__device__ __align__(16) unsigned char g_scratch[32 * TILE_BYTES];

__device__ __forceinline__ void ldsm_x4(uint32_t r[4], uint32_t addr) {
    asm volatile("ldmatrix.sync.aligned.m8n8.x4.shared.b16 {%0,%1,%2,%3}, [%4];"
                 : "=r"(r[0]), "=r"(r[1]), "=r"(r[2]), "=r"(r[3]) : "r"(addr));
}
__device__ __forceinline__ void mma_bf16(float d[4], const uint32_t a[4],
                                         const uint32_t b[2]) {
    asm volatile("mma.sync.aligned.m16n8k16.row.col.f32.bf16.bf16.f32 "
                 "{%0,%1,%2,%3}, {%4,%5,%6,%7}, {%8,%9}, {%0,%1,%2,%3};"
                 : "+f"(d[0]), "+f"(d[1]), "+f"(d[2]), "+f"(d[3])
                 : "r"(a[0]), "r"(a[1]), "r"(a[2]), "r"(a[3]),
                   "r"(b[0]), "r"(b[1]));
}
__device__ __forceinline__ void cp16(uint32_t dst, const void* src) {
    asm volatile("cp.async.ca.shared.global [%0], [%1], 16;"
                 :: "r"(dst), "l"(src) : "memory");
}
#define CP_COMMIT() asm volatile("cp.async.commit_group;" ::: "memory")
#define CP_WAIT0()  asm volatile("cp.async.wait_group 0;" ::: "memory")

__device__ __forceinline__ void cvt_hilo8(float4 a, float4 b, uint4& H, uint4& L) {
    float xs[8] = {a.x, a.y, a.z, a.w, b.x, b.y, b.z, b.w};
    uint32_t h[4], l[4];
#pragma unroll
    for (int i = 0; i < 4; i++) {
        __nv_bfloat16 h0 = __float2bfloat16_rn(xs[2 * i]);
        __nv_bfloat16 h1 = __float2bfloat16_rn(xs[2 * i + 1]);
        __nv_bfloat16 l0 = __float2bfloat16_rn(xs[2 * i]     - __bfloat162float(h0));
        __nv_bfloat16 l1 = __float2bfloat16_rn(xs[2 * i + 1] - __bfloat162float(h1));
        __nv_bfloat162 hp = __halves2bfloat162(h0, h1);
        __nv_bfloat162 lp = __halves2bfloat162(l0, l1);
        h[i] = *reinterpret_cast<uint32_t*>(&hp);
        l[i] = *reinterpret_cast<uint32_t*>(&lp);
    }
    H = make_uint4(h[0], h[1], h[2], h[3]);
    L = make_uint4(l[0], l[1], l[2], l[3]);
}

// ---- kernel 1: im2col + hi/lo split into smem-image scratch ----
__global__ __launch_bounds__(256)
void im2col_prep(const float* __restrict__ gin)
{
    const int tile = blockIdx.x;          // b*8 + tl128
    const int b = tile >> 3, tl = tile & 7;
    const int row = threadIdx.x >> 1, half = threadIdx.x & 1;
    const int pq = tl * 128 + row;
    const int p = pq >> 5, q = pq & 31;
    const float* src = gin + (size_t)b * 16384;
    unsigned char* arow = g_scratch + (size_t)tile * TILE_BYTES + row * STRB;
    const int t0 = half ? 4 : 0, t1 = half ? 9 : 4;
#pragma unroll
    for (int tap = t0; tap < t1; tap++) {
        const int pp = p + tap / 3 - 1, qq = q + tap % 3 - 1;
        float4 a0, a1, a2, a3;
        if ((unsigned)pp < 32u && (unsigned)qq < 32u) {
            const float4* s4 = (const float4*)(src + (pp * 32 + qq) * 16);
            a0 = s4[0]; a1 = s4[1]; a2 = s4[2]; a3 = s4[3];
        } else {
            a0 = a1 = a2 = a3 = make_float4(0.f, 0.f, 0.f, 0.f);
        }
        uint4 H0, L0, H1, L1;
        cvt_hilo8(a0, a1, H0, L0);
        cvt_hilo8(a2, a3, H1, L1);
        *(uint4*)(arow + (tap * 16) * 2)            = H0;
        *(uint4*)(arow + (tap * 16) * 2 + 16)       = H1;
        *(uint4*)(arow + (144 + tap * 16) * 2)      = L0;
        *(uint4*)(arow + (144 + tap * 16) * 2 + 16) = L1;
    }
}

// ---- kernel 2: mainloop, 2 CTAs/SM ----
__global__ __launch_bounds__(256, 2)
void inrf_hmma(const float* __restrict__ gin, const float* __restrict__ gM,
               const float* __restrict__ gW, const float* __restrict__ gG,
               float* __restrict__ gout)
{
    extern __shared__ char smem[];
    const int tid  = threadIdx.x;
    const int wid  = tid >> 5;
    const int lane = tid & 31;
    const int ij0  = blockIdx.x * 8;
    const int by   = blockIdx.y;
    const uint32_t sbase = (uint32_t)__cvta_generic_to_shared(smem);

    // ---- build B: hi -> A0/A1 region (temp, 38912 B, consumed to regs),
    //      lo -> SM_BLO (persistent) ----
    {
        const int row  = tid >> 1;
        const int half = tid & 1;
        const int ijl  = row >> 4, f = row & 15;
        const float* gb = gG + (size_t)(ij0 + ijl) * 2304 + f;
        char* hrow = smem + SM_A0  + row * BSTR;
        char* lrow = smem + SM_BLO + row * BSTR;
        const int t0 = half ? 5 : 0, t1 = half ? 9 : 5;
        for (int tap = t0; tap < t1; tap++) {
            float xs[16];
#pragma unroll
            for (int c = 0; c < 16; c++) xs[c] = gb[(tap * 16 + c) * 16];
            uint4 H0, L0, H1, L1;
            cvt_hilo8(make_float4(xs[0], xs[1], xs[2], xs[3]),
                      make_float4(xs[4], xs[5], xs[6], xs[7]), H0, L0);
            cvt_hilo8(make_float4(xs[8], xs[9], xs[10], xs[11]),
                      make_float4(xs[12], xs[13], xs[14], xs[15]), H1, L1);
            *(uint4*)(hrow + tap * 32)      = H0;
            *(uint4*)(hrow + tap * 32 + 16) = H1;
            *(uint4*)(lrow + tap * 32)      = L0;
            *(uint4*)(lrow + tap * 32 + 16) = L1;
        }
    }
    __syncthreads();

    const uint32_t bRowSel =
        (uint32_t)(wid * 16 + (lane & 7) + ((lane >> 4) << 3)) * BSTR +
        (((lane >> 3) & 1) << 4);
    uint32_t bh[9][4];
    {
        const uint32_t bL4 = sbase + SM_A0 + bRowSel;
#pragma unroll
        for (int s = 0; s < 9; s++) ldsm_x4(bh[s], bL4 + s * 32);
    }
    __syncthreads();   // hi-temp free -> A buffers

    // ---- prefetch chunk 0 ----
    {
        const unsigned char* asrc = g_scratch + (size_t)(by * 2 * 16) * CH;
        for (int i = tid; i < CH / 16; i += 256)
            cp16(sbase + SM_A0 + i * 16, asrc + i * 16);
        CP_COMMIT();
        CP_WAIT0();
    }
    __syncthreads();

    const uint32_t aL   = sbase + (lane & 15) * STRB + (lane >> 4) * 16;
    const uint32_t blL4 = sbase + SM_BLO + bRowSel;
    const float* m2w = gM + (size_t)(ij0 + wid) * 1024;
    const float* w2w = gW + (size_t)(ij0 + wid) * 1024;

    float acc_f[4] = {0.f, 0.f, 0.f, 0.f};

#pragma unroll 1
    for (int t = 0; t < 32; t++) {
        const int b   = by * 2 + (t >> 4);
        const int pqb = (t & 15) * 64;
        const uint32_t abuf = (t & 1) ? SM_A1 : SM_A0;

        // ---- prefetch chunk t+1 ----
        if (t < 31) {
            const int tn = t + 1;
            const int bn = by * 2 + (tn >> 4);
            const uint32_t abn = (tn & 1) ? SM_A1 : SM_A0;
            const unsigned char* asrc =
                g_scratch + (size_t)(bn * 16 + (tn & 15)) * CH;
            for (int i = tid; i < CH / 16; i += 256)
                cp16(sbase + abn + i * 16, asrc + i * 16);
            CP_COMMIT();
        }

        // ---- 9 k-steps over m=64 ----
        float d[4][2][4];
#pragma unroll
        for (int mt = 0; mt < 4; mt++)
#pragma unroll
            for (int nt = 0; nt < 2; nt++)
#pragma unroll
                for (int r = 0; r < 4; r++) d[mt][nt][r] = 0.f;

#pragma unroll 1
        for (int s = 0; s < 9; s++) {
            uint32_t bl4[4];
            ldsm_x4(bl4, blL4 + s * 32);
            const uint32_t base_hi = aL + abuf + (s * 16) * 2;
            const uint32_t base_lo = aL + abuf + (144 + s * 16) * 2;
#pragma unroll
            for (int mt = 0; mt < 4; mt++) {
                uint32_t a[4];
                ldsm_x4(a, base_hi + mt * 16 * STRB);
                mma_bf16(d[mt][0], a, &bh[s][0]);
                mma_bf16(d[mt][1], a, &bh[s][2]);
                mma_bf16(d[mt][0], a, &bl4[0]);
                mma_bf16(d[mt][1], a, &bl4[2]);
            }
#pragma unroll
            for (int mt = 0; mt < 4; mt++) {
                uint32_t a[4];
                ldsm_x4(a, base_lo + mt * 16 * STRB);
                mma_bf16(d[mt][0], a, &bh[s][0]);
                mma_bf16(d[mt][1], a, &bh[s][2]);
            }
        }

        // ---- fused epilogue (x = hi + lo reconstructed from A tile) ----
        {
            const int rl = lane >> 2;
#pragma unroll
            for (int mt = 0; mt < 4; mt++) {
                const int r0 = pqb + mt * 16 + rl;
                const float m2a = __ldg(m2w + r0),     w2a = __ldg(w2w + r0);
                const float m2b = __ldg(m2w + r0 + 8), w2b = __ldg(w2w + r0 + 8);
                const char* ar  = smem + abuf + (mt * 16 + rl) * STRB;
                const char* ar8 = ar + 8 * STRB;
#pragma unroll
                for (int nt = 0; nt < 2; nt++) {
                    const int fb = nt * 8 + 2 * (lane & 3);
                    __nv_bfloat162 h0 = *(const __nv_bfloat162*)(ar  + 128 + 2 * fb);
                    __nv_bfloat162 l0 = *(const __nv_bfloat162*)(ar  + 416 + 2 * fb);
                    __nv_bfloat162 h1 = *(const __nv_bfloat162*)(ar8 + 128 + 2 * fb);
                    __nv_bfloat162 l1 = *(const __nv_bfloat162*)(ar8 + 416 + 2 * fb);
                    float2 hf0 = __bfloat1622float2(h0), lf0 = __bfloat1622float2(l0);
                    float2 hf1 = __bfloat1622float2(h1), lf1 = __bfloat1622float2(l1);
                    const float xa = hf0.x + lf0.x, xb = hf0.y + lf0.y;
                    const float xc = hf1.x + lf1.x, xd = hf1.y + lf1.y;
                    acc_f[nt * 2 + 0] += m2a * xa
                        - w2a * fmaxf(xa - d[mt][nt][0], 0.f);
                    acc_f[nt * 2 + 1] += m2a * xb
                        - w2a * fmaxf(xb - d[mt][nt][1], 0.f);
                    acc_f[nt * 2 + 0] += m2b * xc
                        - w2b * fmaxf(xc - d[mt][nt][2], 0.f);
                    acc_f[nt * 2 + 1] += m2b * xd
                        - w2b * fmaxf(xd - d[mt][nt][3], 0.f);
                }
            }
        }

        if (t < 31) CP_WAIT0();
        __syncthreads();

        // ---- flush per b ----
        if ((t & 15) == 15) {
#pragma unroll
            for (int off = 4; off <= 16; off <<= 1)
#pragma unroll
                for (int j = 0; j < 4; j++)
                    acc_f[j] += __shfl_xor_sync(0xffffffffu, acc_f[j], off);
            if (lane < 4) {
                const int ij = ij0 + wid;
                float* op = gout + ((size_t)b * 1024 + ij) * 16;
#pragma unroll
                for (int nt = 0; nt < 2; nt++)
#pragma unroll
                    for (int par = 0; par < 2; par++)
                        op[nt * 8 + 2 * lane + par] = acc_f[nt * 2 + par];
            }
#pragma unroll
            for (int j = 0; j < 4; j++) acc_f[j] = 0.f;
        }
    }
}

extern "C" void kernel_launch(void* const* d_in, const int* in_sizes, int n_in,
                              void* d_out, int out_size)
{
    const float* inputs = (const float*)d_in[0];
    const float* M      = (const float*)d_in[1];
    const float* Wp     = (const float*)d_in[2];
    const float* G      = (const float*)d_in[3];
    float* out = (float*)d_out;

    im2col_prep<<<32, 256>>>(inputs);

    cudaFuncSetAttribute(inrf_hmma, cudaFuncAttributeMaxDynamicSharedMemorySize, SM_TOT);
    dim3 grid(128, 2);
    inrf_hmma<<<grid, 256, SM_TOT>>>(inputs, M, Wp, G, out);
}

// round 14
// speedup vs baseline: 6.5386x; 2.0283x over previous
#include <cuda_runtime.h>
#include <cuda_fp16.h>
#include <cstdint>

// INRF — round 11: single-pass fp16 HMMA (empirically-anchored rel_err ~1.5e-4),
// m-tile 128 (16 tiles), 2 CTAs/SM, cp.async double-buffered from fp16 im2col
// scratch, B fragments in registers, exact fp32 x streamed for epilogue.

#define STRA 304                  // A/B row stride bytes (144 fp16 = 288 + pad)
#define CH   38912                // 128-row A tile bytes (128*304)
#define XROW 80                   // x row stride bytes (16 floats + pad)

#define SM_A0  0
#define SM_A1  38912
#define SM_X0  77824              // 128*80 = 10240
#define SM_X1  88064
#define SM_TOT 98304              // 96 KB -> 2 CTAs/SM

__device__ __align__(16) unsigned char g_scratch[32 * CH];

__device__ __forceinline__ void ldsm_x4(uint32_t r[4], uint32_t addr) {
    asm volatile("ldmatrix.sync.aligned.m8n8.x4.shared.b16 {%0,%1,%2,%3}, [%4];"
                 : "=r"(r[0]), "=r"(r[1]), "=r"(r[2]), "=r"(r[3]) : "r"(addr));
}
__device__ __forceinline__ void mma_f16(float d[4], const uint32_t a[4],
                                        const uint32_t b[2]) {
    asm volatile("mma.sync.aligned.m16n8k16.row.col.f32.f16.f16.f32 "
                 "{%0,%1,%2,%3}, {%4,%5,%6,%7}, {%8,%9}, {%0,%1,%2,%3};"
                 : "+f"(d[0]), "+f"(d[1]), "+f"(d[2]), "+f"(d[3])
                 : "r"(a[0]), "r"(a[1]), "r"(a[2]), "r"(a[3]),
                   "r"(b[0]), "r"(b[1]));
}
__device__ __forceinline__ void cp16(uint32_t dst, const void* src) {
    asm volatile("cp.async.ca.shared.global [%0], [%1], 16;"
                 :: "r"(dst), "l"(src) : "memory");
}
#define CP_COMMIT() asm volatile("cp.async.commit_group;" ::: "memory")
#define CP_WAIT0()  asm volatile("cp.async.wait_group 0;" ::: "memory")

// 16 floats -> 8 packed half2 as two uint4
__device__ __forceinline__ void cvt_h16(const float4 a, const float4 b,
                                        const float4 c, const float4 dd,
                                        uint4& P0, uint4& P1) {
    __half2 h[8];
    h[0] = __floats2half2_rn(a.x, a.y);  h[1] = __floats2half2_rn(a.z, a.w);
    h[2] = __floats2half2_rn(b.x, b.y);  h[3] = __floats2half2_rn(b.z, b.w);
    h[4] = __floats2half2_rn(c.x, c.y);  h[5] = __floats2half2_rn(c.z, c.w);
    h[6] = __floats2half2_rn(dd.x, dd.y); h[7] = __floats2half2_rn(dd.z, dd.w);
    const uint32_t* u = (const uint32_t*)h;
    P0 = make_uint4(u[0], u[1], u[2], u[3]);
    P1 = make_uint4(u[4], u[5], u[6], u[7]);
}

// ---- kernel 1: fp16 im2col into smem-image scratch ----
__global__ __launch_bounds__(256)
void im2col_prep(const float* __restrict__ gin)
{
    const int tile = blockIdx.x;          // b*8 + tl
    const int b = tile >> 3, tl = tile & 7;
    const int row = threadIdx.x >> 1, half = threadIdx.x & 1;
    const int pq = tl * 128 + row;
    const int p = pq >> 5, q = pq & 31;
    const float* src = gin + (size_t)b * 16384;
    unsigned char* arow = g_scratch + (size_t)tile * CH + row * STRA;
    const int t0 = half ? 4 : 0, t1 = half ? 9 : 4;
#pragma unroll
    for (int tap = t0; tap < t1; tap++) {
        const int pp = p + tap / 3 - 1, qq = q + tap % 3 - 1;
        float4 a0, a1, a2, a3;
        if ((unsigned)pp < 32u && (unsigned)qq < 32u) {
            const float4* s4 = (const float4*)(src + (pp * 32 + qq) * 16);
            a0 = s4[0]; a1 = s4[1]; a2 = s4[2]; a3 = s4[3];
        } else {
            a0 = a1 = a2 = a3 = make_float4(0.f, 0.f, 0.f, 0.f);
        }
        uint4 P0, P1;
        cvt_h16(a0, a1, a2, a3, P0, P1);
        *(uint4*)(arow + tap * 32)      = P0;
        *(uint4*)(arow + tap * 32 + 16) = P1;
    }
}

// ---- kernel 2: mainloop ----
__global__ __launch_bounds__(256, 2)
void inrf_hmma(const float* __restrict__ gin, const float* __restrict__ gM,
               const float* __restrict__ gW, const float* __restrict__ gG,
               float* __restrict__ gout)
{
    extern __shared__ char smem[];
    const int tid  = threadIdx.x;
    const int wid  = tid >> 5;
    const int lane = tid & 31;
    const int ij0  = blockIdx.x * 8;
    const int by   = blockIdx.y;
    const uint32_t sbase = (uint32_t)__cvta_generic_to_shared(smem);

    // ---- build B[128x144] fp16 in A region (temp), load to regs ----
    {
        const int row  = tid >> 1;
        const int half = tid & 1;
        const int ijl  = row >> 4, f = row & 15;
        const float* gb = gG + (size_t)(ij0 + ijl) * 2304 + f;
        char* brow = smem + SM_A0 + row * STRA;
        const int t0 = half ? 5 : 0, t1 = half ? 9 : 5;
        for (int tap = t0; tap < t1; tap++) {
            float xs[16];
#pragma unroll
            for (int c = 0; c < 16; c++) xs[c] = gb[(tap * 16 + c) * 16];
            uint4 P0, P1;
            cvt_h16(make_float4(xs[0], xs[1], xs[2], xs[3]),
                    make_float4(xs[4], xs[5], xs[6], xs[7]),
                    make_float4(xs[8], xs[9], xs[10], xs[11]),
                    make_float4(xs[12], xs[13], xs[14], xs[15]), P0, P1);
            *(uint4*)(brow + tap * 32)      = P0;
            *(uint4*)(brow + tap * 32 + 16) = P1;
        }
    }
    __syncthreads();

    uint32_t bh[9][4];
    {
        const uint32_t bL4 = sbase + SM_A0 +
            (uint32_t)(wid * 16 + (lane & 7) + ((lane >> 4) << 3)) * STRA +
            (((lane >> 3) & 1) << 4);
#pragma unroll
        for (int s = 0; s < 9; s++) ldsm_x4(bh[s], bL4 + s * 32);
    }
    __syncthreads();   // B temp free -> A buffers

    // ---- prefetch tile 0 (A image + exact x) ----
    {
        const unsigned char* asrc = g_scratch + (size_t)(by * 2 * 8) * CH;
        for (int i = tid; i < CH / 16; i += 256)
            cp16(sbase + SM_A0 + i * 16, asrc + i * 16);
        const char* xsrc = (const char*)(gin + (size_t)(by * 2) * 16384);
        for (int i = tid; i < 512; i += 256)
            cp16(sbase + SM_X0 + (i >> 2) * XROW + (i & 3) * 16, xsrc + i * 16);
        CP_COMMIT();
        CP_WAIT0();
    }
    __syncthreads();

    const uint32_t aL = sbase + (lane & 15) * STRA + (lane >> 4) * 16;
    const float* m2w = gM + (size_t)(ij0 + wid) * 1024;
    const float* w2w = gW + (size_t)(ij0 + wid) * 1024;

    float acc_f[4] = {0.f, 0.f, 0.f, 0.f};

#pragma unroll 1
    for (int t = 0; t < 16; t++) {
        const int b   = by * 2 + (t >> 3);
        const int pqb = (t & 7) * 128;
        const uint32_t abuf = (t & 1) ? SM_A1 : SM_A0;
        const uint32_t xbuf = (t & 1) ? SM_X1 : SM_X0;

        // ---- prefetch tile t+1 ----
        if (t < 15) {
            const int tn = t + 1;
            const int bn = by * 2 + (tn >> 3);
            const uint32_t abn = (tn & 1) ? SM_A1 : SM_A0;
            const uint32_t xbn = (tn & 1) ? SM_X1 : SM_X0;
            const unsigned char* asrc =
                g_scratch + (size_t)(bn * 8 + (tn & 7)) * CH;
            for (int i = tid; i < CH / 16; i += 256)
                cp16(sbase + abn + i * 16, asrc + i * 16);
            const char* xsrc =
                (const char*)(gin + ((size_t)bn * 1024 + (tn & 7) * 128) * 16);
            for (int i = tid; i < 512; i += 256)
                cp16(sbase + xbn + (i >> 2) * XROW + (i & 3) * 16, xsrc + i * 16);
            CP_COMMIT();
        }

        // ---- 9 k-steps, single fp16 pass ----
        float d[8][2][4];
#pragma unroll
        for (int mt = 0; mt < 8; mt++)
#pragma unroll
            for (int nt = 0; nt < 2; nt++)
#pragma unroll
                for (int r = 0; r < 4; r++) d[mt][nt][r] = 0.f;

#pragma unroll 1
        for (int s = 0; s < 9; s++) {
            const uint32_t base = aL + abuf + s * 32;
#pragma unroll
            for (int mt = 0; mt < 8; mt++) {
                uint32_t a[4];
                ldsm_x4(a, base + mt * 16 * STRA);
                mma_f16(d[mt][0], a, &bh[s][0]);
                mma_f16(d[mt][1], a, &bh[s][2]);
            }
        }

        // ---- fused epilogue (exact fp32 x from X buffer) ----
        {
            const int rl = lane >> 2;
            const char* xb = smem + xbuf;
#pragma unroll
            for (int mt = 0; mt < 8; mt++) {
                const int r0 = pqb + mt * 16 + rl;
                const float m2a = __ldg(m2w + r0),     w2a = __ldg(w2w + r0);
                const float m2b = __ldg(m2w + r0 + 8), w2b = __ldg(w2w + r0 + 8);
                const char* xr  = xb + (mt * 16 + rl) * XROW;
                const char* xr8 = xr + 8 * XROW;
#pragma unroll
                for (int nt = 0; nt < 2; nt++) {
                    const int fb = nt * 8 + 2 * (lane & 3);
                    const float2 xlo = *(const float2*)(xr  + fb * 4);
                    const float2 xhi = *(const float2*)(xr8 + fb * 4);
                    acc_f[nt * 2 + 0] += m2a * xlo.x
                        - w2a * fmaxf(xlo.x - d[mt][nt][0], 0.f);
                    acc_f[nt * 2 + 1] += m2a * xlo.y
                        - w2a * fmaxf(xlo.y - d[mt][nt][1], 0.f);
                    acc_f[nt * 2 + 0] += m2b * xhi.x
                        - w2b * fmaxf(xhi.x - d[mt][nt][2], 0.f);
                    acc_f[nt * 2 + 1] += m2b * xhi.y
                        - w2b * fmaxf(xhi.y - d[mt][nt][3], 0.f);
                }
            }
        }

        if (t < 15) CP_WAIT0();
        __syncthreads();

        // ---- flush per b ----
        if ((t & 7) == 7) {
#pragma unroll
            for (int off = 4; off <= 16; off <<= 1)
#pragma unroll
                for (int j = 0; j < 4; j++)
                    acc_f[j] += __shfl_xor_sync(0xffffffffu, acc_f[j], off);
            if (lane < 4) {
                const int ij = ij0 + wid;
                float* op = gout + ((size_t)b * 1024 + ij) * 16;
#pragma unroll
                for (int nt = 0; nt < 2; nt++)
#pragma unroll
                    for (int par = 0; par < 2; par++)
                        op[nt * 8 + 2 * lane + par] = acc_f[nt * 2 + par];
            }
#pragma unroll
            for (int j = 0; j < 4; j++) acc_f[j] = 0.f;
        }
    }
}

extern "C" void kernel_launch(void* const* d_in, const int* in_sizes, int n_in,
                              void* d_out, int out_size)
{
    const float* inputs = (const float*)d_in[0];
    const float* M      = (const float*)d_in[1];
    const float* Wp     = (const float*)d_in[2];
    const float* G      = (const float*)d_in[3];
    float* out = (float*)d_out;

    im2col_prep<<<32, 256>>>(inputs);

    cudaFuncSetAttribute(inrf_hmma, cudaFuncAttributeMaxDynamicSharedMemorySize, SM_TOT);
    dim3 grid(128, 2);
    inrf_hmma<<<grid, 256, SM_TOT>>>(inputs, M, Wp, G, out);
}